// round 1
// baseline (speedup 1.0000x reference)
#include <cuda_runtime.h>

#define NXD 1024
#define NYD 1024
#define BD  16

// 1st-derivative edge-order-2 stencil coefficients at position i in [0,N)
__device__ __forceinline__ void gcoef1(int i, int N, int idx[3], float c[3], int& n) {
    if (i == 0)          { idx[0]=0;   idx[1]=1;   idx[2]=2;   c[0]=-1.5f; c[1]= 2.0f; c[2]=-0.5f; n=3; }
    else if (i == N - 1) { idx[0]=N-1; idx[1]=N-2; idx[2]=N-3; c[0]= 1.5f; c[1]=-2.0f; c[2]= 0.5f; n=3; }
    else                 { idx[0]=i-1; idx[1]=i+1; c[0]=-0.5f; c[1]=0.5f; n=2; }
}

// 2nd-derivative stencil coefficients
__device__ __forceinline__ void gcoef2(int i, int N, int idx[4], float c[4], int& n) {
    if (i == 0)          { idx[0]=0;   idx[1]=1;   idx[2]=2;   idx[3]=3;   c[0]=2.0f; c[1]=-5.0f; c[2]=4.0f; c[3]=-1.0f; n=4; }
    else if (i == N - 1) { idx[0]=N-1; idx[1]=N-2; idx[2]=N-3; idx[3]=N-4; c[0]=2.0f; c[1]=-5.0f; c[2]=4.0f; c[3]=-1.0f; n=4; }
    else                 { idx[0]=i-1; idx[1]=i;   idx[2]=i+1; c[0]=1.0f; c[1]=-2.0f; c[2]=1.0f; n=3; }
}

__global__ void __launch_bounds__(256) fp2d_kernel(
    const float* __restrict__ f,      // [B, NX, NY]
    const float* __restrict__ Agrid,  // [2, NX, NY]
    const float* __restrict__ Bgrid,  // [3, NX, NY]
    const float* __restrict__ dt,     // [B]
    float* __restrict__ out)          // [B, NX, NY]
{
    const int y = blockIdx.x * 32 + threadIdx.x;
    const int x = blockIdx.y * 8  + threadIdx.y;
    const int b = blockIdx.z;
    if (x >= NXD || y >= NYD) return;

    const float* __restrict__ Fb = f + (size_t)b * NXD * NYD;
    const float* __restrict__ A0 = Agrid;
    const float* __restrict__ A1 = Agrid + NXD * NYD;
    const float* __restrict__ B0 = Bgrid;
    const float* __restrict__ B1 = Bgrid + NXD * NYD;
    const float* __restrict__ B2 = Bgrid + 2 * NXD * NYD;

    int ix1[3]; float cx1[3]; int nx1;
    int iy1[3]; float cy1[3]; int ny1;
    gcoef1(x, NXD, ix1, cx1, nx1);
    gcoef1(y, NYD, iy1, cy1, ny1);

    int ix2[4]; float cx2[4]; int nx2;
    int iy2[4]; float cy2[4]; int ny2;
    gcoef2(x, NXD, ix2, cx2, nx2);
    gcoef2(y, NYD, iy2, cy2, ny2);

    // -- advection term: grad_x(A0 f) + grad_y(A1 f) --
    float ga = 0.0f;
    #pragma unroll
    for (int j = 0; j < 3; ++j) {
        if (j < nx1) {
            int k = ix1[j] * NYD + y;
            ga += cx1[j] * __ldg(&A0[k]) * __ldg(&Fb[k]);
        }
    }
    #pragma unroll
    for (int j = 0; j < 3; ++j) {
        if (j < ny1) {
            int k = x * NYD + iy1[j];
            ga += cy1[j] * __ldg(&A1[k]) * __ldg(&Fb[k]);
        }
    }

    // -- diffusion: grad2_x(B0 f) + grad2_y(B1 f) --
    float gb = 0.0f;
    #pragma unroll
    for (int j = 0; j < 4; ++j) {
        if (j < nx2) {
            int k = ix2[j] * NYD + y;
            gb += cx2[j] * __ldg(&B0[k]) * __ldg(&Fb[k]);
        }
    }
    #pragma unroll
    for (int j = 0; j < 4; ++j) {
        if (j < ny2) {
            int k = x * NYD + iy2[j];
            gb += cy2[j] * __ldg(&B1[k]) * __ldg(&Fb[k]);
        }
    }

    // -- cross term: grad_x(grad_y(B2 f)) + grad_y(grad_x(B2 f)) == 2 * tensor-product stencil --
    float gc = 0.0f;
    #pragma unroll
    for (int j = 0; j < 3; ++j) {
        if (j < nx1) {
            float acc = 0.0f;
            #pragma unroll
            for (int k = 0; k < 3; ++k) {
                if (k < ny1) {
                    int idx = ix1[j] * NYD + iy1[k];
                    acc += cy1[k] * __ldg(&B2[idx]) * __ldg(&Fb[idx]);
                }
            }
            gc += cx1[j] * acc;
        }
    }
    gb += 2.0f * gc;

    const int ic = x * NYD + y;
    float df = -ga + 0.5f * gb;
    float val = __ldg(&Fb[ic]) + df * __ldg(&dt[b]);
    out[(size_t)b * NXD * NYD + ic] = fmaxf(val, 0.0f);
}

extern "C" void kernel_launch(void* const* d_in, const int* in_sizes, int n_in,
                              void* d_out, int out_size) {
    const float* f  = (const float*)d_in[0];
    const float* Ag = (const float*)d_in[1];
    const float* Bg = (const float*)d_in[2];
    const float* dt = (const float*)d_in[3];
    float* out = (float*)d_out;

    dim3 block(32, 8, 1);
    dim3 grid(NYD / 32, NXD / 8, BD);
    fp2d_kernel<<<grid, block>>>(f, Ag, Bg, dt, out);
}

// round 2
// speedup vs baseline: 2.3315x; 2.3315x over previous
#include <cuda_runtime.h>

#define NXD 1024
#define NYD 1024
#define BD  16
#define NP  (NXD * NYD)

// ---- generic (boundary) helpers: edge-order-2 one-sided stencils ----
__device__ __forceinline__ void gcoef1(int i, int N, int idx[3], float c[3], int& n) {
    if (i == 0)          { idx[0]=0;   idx[1]=1;   idx[2]=2;   c[0]=-1.5f; c[1]= 2.0f; c[2]=-0.5f; n=3; }
    else if (i == N - 1) { idx[0]=N-1; idx[1]=N-2; idx[2]=N-3; c[0]= 1.5f; c[1]=-2.0f; c[2]= 0.5f; n=3; }
    else                 { idx[0]=i-1; idx[1]=i+1; c[0]=-0.5f; c[1]=0.5f; n=2; }
}

__device__ __forceinline__ void gcoef2(int i, int N, int idx[4], float c[4], int& n) {
    if (i == 0)          { idx[0]=0;   idx[1]=1;   idx[2]=2;   idx[3]=3;   c[0]=2.0f; c[1]=-5.0f; c[2]=4.0f; c[3]=-1.0f; n=4; }
    else if (i == N - 1) { idx[0]=N-1; idx[1]=N-2; idx[2]=N-3; idx[3]=N-4; c[0]=2.0f; c[1]=-5.0f; c[2]=4.0f; c[3]=-1.0f; n=4; }
    else                 { idx[0]=i-1; idx[1]=i;   idx[2]=i+1; c[0]=1.0f; c[1]=-2.0f; c[2]=1.0f; n=3; }
}

__device__ float generic_df(const float* __restrict__ Fb,
                            const float* __restrict__ A0, const float* __restrict__ A1,
                            const float* __restrict__ B0, const float* __restrict__ B1,
                            const float* __restrict__ B2, int x, int y)
{
    int ix1[3]; float cx1[3]; int nx1;
    int iy1[3]; float cy1[3]; int ny1;
    gcoef1(x, NXD, ix1, cx1, nx1);
    gcoef1(y, NYD, iy1, cy1, ny1);

    int ix2[4]; float cx2[4]; int nx2;
    int iy2[4]; float cy2[4]; int ny2;
    gcoef2(x, NXD, ix2, cx2, nx2);
    gcoef2(y, NYD, iy2, cy2, ny2);

    float ga = 0.0f;
    #pragma unroll
    for (int j = 0; j < 3; ++j)
        if (j < nx1) { int k = ix1[j] * NYD + y; ga += cx1[j] * __ldg(&A0[k]) * __ldg(&Fb[k]); }
    #pragma unroll
    for (int j = 0; j < 3; ++j)
        if (j < ny1) { int k = x * NYD + iy1[j]; ga += cy1[j] * __ldg(&A1[k]) * __ldg(&Fb[k]); }

    float gb = 0.0f;
    #pragma unroll
    for (int j = 0; j < 4; ++j)
        if (j < nx2) { int k = ix2[j] * NYD + y; gb += cx2[j] * __ldg(&B0[k]) * __ldg(&Fb[k]); }
    #pragma unroll
    for (int j = 0; j < 4; ++j)
        if (j < ny2) { int k = x * NYD + iy2[j]; gb += cy2[j] * __ldg(&B1[k]) * __ldg(&Fb[k]); }

    float gc = 0.0f;
    #pragma unroll
    for (int j = 0; j < 3; ++j)
        if (j < nx1) {
            float acc = 0.0f;
            #pragma unroll
            for (int k = 0; k < 3; ++k)
                if (k < ny1) {
                    int idx = ix1[j] * NYD + iy1[k];
                    acc += cy1[k] * __ldg(&B2[idx]) * __ldg(&Fb[idx]);
                }
            gc += cx1[j] * acc;
        }
    return -ga + 0.5f * gb + gc;
}

// ---- main kernel: interior fast path with precomputed 9-pt weights, batch loop ----
__global__ void __launch_bounds__(256) fp2d_kernel(
    const float* __restrict__ f,      // [B, NX, NY]
    const float* __restrict__ Agrid,  // [2, NX, NY]
    const float* __restrict__ Bgrid,  // [3, NX, NY]
    const float* __restrict__ dt,     // [B]
    float* __restrict__ out)          // [B, NX, NY]
{
    const int ty = blockIdx.x * 32 + threadIdx.x;     // pair index along y
    const int y0 = ty * 2;                            // even
    const int x  = blockIdx.y * 8 + threadIdx.y;

    const float* __restrict__ A0 = Agrid;
    const float* __restrict__ A1 = Agrid + NP;
    const float* __restrict__ B0 = Bgrid;
    const float* __restrict__ B1 = Bgrid + NP;
    const float* __restrict__ B2 = Bgrid + 2 * NP;

    const bool interior = (x >= 1) && (x <= NXD - 2) && (y0 >= 2) && (y0 <= NYD - 4) ? true
                        : ((x >= 1) && (x <= NXD - 2) && (y0 >= 1) && (y0 + 1 <= NYD - 2));

    if (interior) {
        const int base = x * NYD + y0;
        const int bm = base - NYD, bc = base, bp = base + NYD;

        // --- batch-invariant grid loads ---
        float a0m  = __ldg(&A0[bm]),   a0m1 = __ldg(&A0[bm + 1]);
        float a0p  = __ldg(&A0[bp]),   a0p1 = __ldg(&A0[bp + 1]);
        float a1v[4], b1v[4], b2m[4], b2p[4];
        #pragma unroll
        for (int j = 0; j < 4; ++j) {
            a1v[j] = __ldg(&A1[bc - 1 + j]);
            b1v[j] = __ldg(&B1[bc - 1 + j]);
            b2m[j] = __ldg(&B2[bm - 1 + j]);
            b2p[j] = __ldg(&B2[bp - 1 + j]);
        }
        float b0m  = __ldg(&B0[bm]),  b0m1 = __ldg(&B0[bm + 1]);
        float b0c  = __ldg(&B0[bc]),  b0c1 = __ldg(&B0[bc + 1]);
        float b0p  = __ldg(&B0[bp]),  b0p1 = __ldg(&B0[bp + 1]);

        // --- weights, point 0 (y0) ---
        const float w0_mm = 0.25f * b2m[0];
        const float w0_mp = -0.25f * b2m[2];
        const float w0_pm = -0.25f * b2p[0];
        const float w0_pp = 0.25f * b2p[2];
        const float w0_m0 = 0.5f * (a0m + b0m);
        const float w0_p0 = 0.5f * (b0p - a0p);
        const float w0_0m = 0.5f * (a1v[0] + b1v[0]);
        const float w0_0p = 0.5f * (b1v[2] - a1v[2]);
        const float w0_00 = -(b0c + b1v[1]);
        // --- weights, point 1 (y0+1) ---
        const float w1_mm = 0.25f * b2m[1];
        const float w1_mp = -0.25f * b2m[3];
        const float w1_pm = -0.25f * b2p[1];
        const float w1_pp = 0.25f * b2p[3];
        const float w1_m0 = 0.5f * (a0m1 + b0m1);
        const float w1_p0 = 0.5f * (b0p1 - a0p1);
        const float w1_0m = 0.5f * (a1v[1] + b1v[1]);
        const float w1_0p = 0.5f * (b1v[3] - a1v[3]);
        const float w1_00 = -(b0c1 + b1v[2]);

        #pragma unroll 4
        for (int b = 0; b < BD; ++b) {
            const float* __restrict__ Fb = f + b * NP;
            const float dtb = __ldg(&dt[b]);
            // rows: cols y0-1 .. y0+2 ; middle pair is 8B-aligned -> float2
            float  rm0 = __ldg(&Fb[bm - 1]);
            float2 rmv = __ldg((const float2*)&Fb[bm]);
            float  rm3 = __ldg(&Fb[bm + 2]);
            float  rc0 = __ldg(&Fb[bc - 1]);
            float2 rcv = __ldg((const float2*)&Fb[bc]);
            float  rc3 = __ldg(&Fb[bc + 2]);
            float  rp0 = __ldg(&Fb[bp - 1]);
            float2 rpv = __ldg((const float2*)&Fb[bp]);
            float  rp3 = __ldg(&Fb[bp + 2]);

            float df0 = w0_mm * rm0;
            df0 = fmaf(w0_m0, rmv.x, df0);
            df0 = fmaf(w0_mp, rmv.y, df0);
            df0 = fmaf(w0_0m, rc0,   df0);
            df0 = fmaf(w0_00, rcv.x, df0);
            df0 = fmaf(w0_0p, rcv.y, df0);
            df0 = fmaf(w0_pm, rp0,   df0);
            df0 = fmaf(w0_p0, rpv.x, df0);
            df0 = fmaf(w0_pp, rpv.y, df0);

            float df1 = w1_mm * rmv.x;
            df1 = fmaf(w1_m0, rmv.y, df1);
            df1 = fmaf(w1_mp, rm3,   df1);
            df1 = fmaf(w1_0m, rcv.x, df1);
            df1 = fmaf(w1_00, rcv.y, df1);
            df1 = fmaf(w1_0p, rc3,   df1);
            df1 = fmaf(w1_pm, rpv.x, df1);
            df1 = fmaf(w1_p0, rpv.y, df1);
            df1 = fmaf(w1_pp, rp3,   df1);

            float2 o;
            o.x = fmaxf(fmaf(df0, dtb, rcv.x), 0.0f);
            o.y = fmaxf(fmaf(df1, dtb, rcv.y), 0.0f);
            *(float2*)&out[b * NP + base] = o;
        }
    } else {
        // boundary: generic per-point path
        #pragma unroll
        for (int s = 0; s < 2; ++s) {
            const int y = y0 + s;
            if (y >= NYD) continue;
            const int base = x * NYD + y;
            for (int b = 0; b < BD; ++b) {
                const float* __restrict__ Fb = f + b * NP;
                float df = generic_df(Fb, A0, A1, B0, B1, B2, x, y);
                float v = fmaf(df, __ldg(&dt[b]), __ldg(&Fb[base]));
                out[b * NP + base] = fmaxf(v, 0.0f);
            }
        }
    }
}

extern "C" void kernel_launch(void* const* d_in, const int* in_sizes, int n_in,
                              void* d_out, int out_size) {
    const float* f  = (const float*)d_in[0];
    const float* Ag = (const float*)d_in[1];
    const float* Bg = (const float*)d_in[2];
    const float* dt = (const float*)d_in[3];
    float* out = (float*)d_out;

    dim3 block(32, 8, 1);
    dim3 grid(NYD / 64, NXD / 8, 1);   // 2 y-points per thread
    fp2d_kernel<<<grid, block>>>(f, Ag, Bg, dt, out);
}